// round 7
// baseline (speedup 1.0000x reference)
#include <cuda_runtime.h>
#include <cuda_bf16.h>

// 3x3 median filter, zero padding, exact median of 9.
// x: (32, 3, 512, 512) fp32 -> 96 images of 512x512.
//
// Block = 256 threads = 512 cols x 16 output rows of one image.
// Phase 1: cooperatively stage all 18 input rows (y0-1 .. y0+16, clamped &
//   zero-masked) into shared memory: 9 coalesced LDG.128 per thread, one
//   front-batched global stall per block.
// Phase 2: thread (t, r) computes 4 cols x 8 output rows from smem.
//   Neighbor columns come from smem (rows padded to 520 floats, zero slots
//   at [512] and [519] implement the horizontal zero-pad branch-free).
//   Rolling row-pairs share sort2 of the middle rows; sliding windows share
//   pair min/max. Exact network, ~15 FMNMX/px.

#define W 512
#define H 512
#define NIMG 96
#define RS 520          // smem row stride in floats (16B-aligned: 520*4=2080)
#define INROWS 18       // input rows per block
#define OUTROWS 16      // output rows per block

__device__ __forceinline__ float med3(float a, float b, float c) {
    return fmaxf(fminf(a, b), fminf(fmaxf(a, b), c));
}

// Read 6-column window of smem row j: cols (4t-1 .. 4t+4) in padded space.
__device__ __forceinline__ void srow(const float* __restrict__ s, int j,
                                     int li, int ri, int t4, float* c) {
    const float* rp = s + j * RS;
    const float4 v = *reinterpret_cast<const float4*>(rp + t4);
    c[0] = rp[li];
    c[1] = v.x; c[2] = v.y; c[3] = v.z; c[4] = v.w;
    c[5] = rp[ri];
}

// Emit one output row: insert row a into (mn, mx) = sort2 of the other two
// rows, combine 3-wide windows with pair sharing, store one float4.
__device__ __forceinline__ void emit_row(const float* a, const float* mn,
                                         const float* mx,
                                         float* __restrict__ outp) {
    float lo[6], mi[6], hi[6];
    #pragma unroll
    for (int i = 0; i < 6; i++) {
        lo[i] = fminf(a[i], mn[i]);
        hi[i] = fmaxf(a[i], mx[i]);
        mi[i] = fmaxf(mn[i], fminf(a[i], mx[i]));
    }
    float o[4];
    #pragma unroll
    for (int t = 0; t < 2; t++) {
        const int i = 2 * t + 1;
        const float A = fmaxf(lo[i], lo[i + 1]);
        const float B = fminf(hi[i], hi[i + 1]);
        const float n = fminf(mi[i], mi[i + 1]);
        const float m = fmaxf(mi[i], mi[i + 1]);
        o[2 * t]     = med3(fmaxf(A, lo[2 * t]),
                            fmaxf(n, fminf(m, mi[2 * t])),
                            fminf(B, hi[2 * t]));
        o[2 * t + 1] = med3(fmaxf(A, lo[2 * t + 3]),
                            fminf(m, fmaxf(n, mi[2 * t + 3])),
                            fminf(B, hi[2 * t + 3]));
    }
    float4 res; res.x = o[0]; res.y = o[1]; res.z = o[2]; res.w = o[3];
    *reinterpret_cast<float4*>(outp) = res;
}

__global__ void __launch_bounds__(256, 5)
median3x3_kernel(const float* __restrict__ x, float* __restrict__ out) {
    __shared__ float s[INROWS * RS];   // 37,440 B

    const int tid = threadIdx.x;
    const int bid = blockIdx.x;
    const int y0  = (bid & 31) << 4;                    // block top output row
    const size_t ibase = (size_t)(bid >> 5) * (H * W);  // image base
    const float* img = x + ibase;
    float* oimg = out + ibase;

    // ---- Phase 1: stage 18 rows into smem (coalesced, front-batched) ----
    #pragma unroll
    for (int k = 0; k < 9; k++) {
        const int idx = tid + (k << 8);        // 0 .. 2303
        const int j   = idx >> 7;              // smem row 0..17
        const int c4  = (idx & 127) << 2;      // col 0..508
        const int gy  = y0 - 1 + j;
        const float mrow = (gy >= 0 && gy < H) ? 1.0f : 0.0f;
        const int gyc = min(max(gy, 0), H - 1);
        float4 v = *reinterpret_cast<const float4*>(img + (size_t)gyc * W + c4);
        v.x *= mrow; v.y *= mrow; v.z *= mrow; v.w *= mrow;
        *reinterpret_cast<float4*>(s + j * RS + c4) = v;
    }
    // zero-pad slots for horizontal edges
    if (tid < INROWS) {
        s[tid * RS + 512] = 0.0f;   // right neighbor of col 511
        s[tid * RS + 519] = 0.0f;   // left  neighbor of col 0
    }
    __syncthreads();

    // ---- Phase 2: compute 4 cols x 8 output rows per thread ----
    const int t  = tid & 127;          // column thread
    const int r  = tid >> 7;           // row half (0 or 1)
    const int t4 = t << 2;             // aligned col base 0..508
    const int li = (t == 0)   ? 519 : t4 - 1;
    const int ri = t4 + 4;             // == 512 (zero) when t == 127
    const int j0 = r << 3;             // first smem row for this half

    float ra[6], rb[6], rc[6], rd[6], mn[6], mx[6];
    srow(s, j0 + 0, li, ri, t4, ra);
    srow(s, j0 + 1, li, ri, t4, rb);

    float* op = oimg + (size_t)(y0 + (r << 3)) * W + t4;

    #pragma unroll
    for (int p = 0; p < 4; p++) {
        srow(s, j0 + 2 * p + 2, li, ri, t4, rc);
        srow(s, j0 + 2 * p + 3, li, ri, t4, rd);

        #pragma unroll
        for (int i = 0; i < 6; i++) {          // rb dead after this
            mn[i] = fminf(rb[i], rc[i]);
            mx[i] = fmaxf(rb[i], rc[i]);
        }
        emit_row(ra, mn, mx, op);              // output row 2p
        emit_row(rd, mn, mx, op + W);          // output row 2p+1
        op += 2 * W;

        // roll: next pair's (top, m1) = (rc, rd)
        #pragma unroll
        for (int i = 0; i < 6; i++) { ra[i] = rc[i]; rb[i] = rd[i]; }
    }
}

extern "C" void kernel_launch(void* const* d_in, const int* in_sizes, int n_in,
                              void* d_out, int out_size) {
    const float* x = (const float*)d_in[0];
    float* out = (float*)d_out;

    const int grid = NIMG * (H / OUTROWS);   // 96 * 32 = 3072
    median3x3_kernel<<<grid, 256>>>(x, out);
}

// round 8
// speedup vs baseline: 1.1045x; 1.1045x over previous
#include <cuda_runtime.h>
#include <cuda_bf16.h>

// 3x3 median filter, zero padding, exact median of 9.
// x: (32, 3, 512, 512) fp32 -> 96 images of 512x512.
//
// Thread = 4 columns x 4 output rows (16 px), register-resident (no smem).
// Software-pipelined: rows for the second output pair (re, rf) are loaded
// BEFORE the first pair's emits, so their global latency hides behind
// ~120 min/max ops instead of stalling. One stall window per strip.
// Zero-padding via clamped addresses + exact 0/1 FMUL masks (fma pipe).
// Exact min/max network, ~15 FMNMX/px, 1.125 loads/px.

#define W 512
#define H 512
#define NIMG 96

__device__ __forceinline__ float med3(float a, float b, float c) {
    return fmaxf(fminf(a, b), fminf(fmaxf(a, b), c));
}

// Load one row's 6-column window (cb-1 .. cb+4), clamped addresses.
template <bool MASK_ROW>
__device__ __forceinline__ void load_row(const float* __restrict__ rowp,
                                         int cb, int cl, int cr,
                                         float ml, float mr, float mrow,
                                         float* c) {
    const float4 v = *reinterpret_cast<const float4*>(rowp + cb);
    const float l = __ldg(rowp + cl);
    const float r = __ldg(rowp + cr);
    if (MASK_ROW) {
        c[0] = l * (ml * mrow);
        c[1] = v.x * mrow; c[2] = v.y * mrow;
        c[3] = v.z * mrow; c[4] = v.w * mrow;
        c[5] = r * (mr * mrow);
    } else {
        c[0] = l * ml;
        c[1] = v.x; c[2] = v.y; c[3] = v.z; c[4] = v.w;
        c[5] = r * mr;
    }
}

// Emit one output row: insert row a into (mn, mx) = sort2 of the other two
// rows, combine 3-wide windows with pair sharing, store one float4.
__device__ __forceinline__ void emit_row(const float* a, const float* mn,
                                         const float* mx,
                                         float* __restrict__ outp) {
    float lo[6], mi[6], hi[6];
    #pragma unroll
    for (int i = 0; i < 6; i++) {
        lo[i] = fminf(a[i], mn[i]);
        hi[i] = fmaxf(a[i], mx[i]);
        mi[i] = fmaxf(mn[i], fminf(a[i], mx[i]));
    }
    float o[4];
    #pragma unroll
    for (int t = 0; t < 2; t++) {
        const int i = 2 * t + 1;
        const float A = fmaxf(lo[i], lo[i + 1]);
        const float B = fminf(hi[i], hi[i + 1]);
        const float n = fminf(mi[i], mi[i + 1]);
        const float m = fmaxf(mi[i], mi[i + 1]);
        o[2 * t]     = med3(fmaxf(A, lo[2 * t]),
                            fmaxf(n, fminf(m, mi[2 * t])),
                            fminf(B, hi[2 * t]));
        o[2 * t + 1] = med3(fmaxf(A, lo[2 * t + 3]),
                            fminf(m, fmaxf(n, mi[2 * t + 3])),
                            fminf(B, hi[2 * t + 3]));
    }
    float4 res; res.x = o[0]; res.y = o[1]; res.z = o[2]; res.w = o[3];
    *reinterpret_cast<float4*>(outp) = res;
}

__global__ void __launch_bounds__(256, 5)
median3x3_kernel(const float* __restrict__ x, float* __restrict__ out) {
    const int tid = blockIdx.x * blockDim.x + threadIdx.x;
    const int cb  = (tid & 127) << 2;          // column base (0..508)
    const int sid = tid >> 7;                  // strip id
    const int y0  = (sid & 127) << 2;          // strip top output row (step 4)
    const size_t ibase = (size_t)(sid >> 7) * (H * W);
    const float* img = x + ibase;
    float* oimg = out + ibase;

    const int cl = (cb == 0)     ? 0     : cb - 1;
    const int cr = (cb == W - 4) ? W - 1 : cb + 4;
    const float ml = (cb > 0)     ? 1.0f : 0.0f;
    const float mr = (cb < W - 4) ? 1.0f : 0.0f;

    const float mt = (y0 > 0)     ? 1.0f : 0.0f;   // row y0-1 valid
    const float mb = (y0 < H - 4) ? 1.0f : 0.0f;   // row y0+4 valid

    float ra[6], rb[6], rc[6], rd[6], re[6], rf[6];
    float mn[6], mx[6];

    // Front batch: rows y0-1 .. y0+2 (pair 0 inputs).
    load_row<true >(img + (y0 > 0 ? y0 - 1 : 0) * W, cb, cl, cr, ml, mr, mt, ra);
    load_row<false>(img + (y0    ) * W, cb, cl, cr, ml, mr, 1.0f, rb);
    load_row<false>(img + (y0 + 1) * W, cb, cl, cr, ml, mr, 1.0f, rc);
    load_row<false>(img + (y0 + 2) * W, cb, cl, cr, ml, mr, 1.0f, rd);

    // sort2 of middle rows (rb dead after this)
    #pragma unroll
    for (int i = 0; i < 6; i++) {
        mn[i] = fminf(rb[i], rc[i]);
        mx[i] = fmaxf(rb[i], rc[i]);
    }

    // PREFETCH pair-1 rows NOW — latency hides behind the two emits below.
    load_row<false>(img + (y0 + 3) * W, cb, cl, cr, ml, mr, 1.0f, re);
    load_row<true >(img + (y0 + 4 < H ? y0 + 4 : H - 1) * W, cb, cl, cr, ml, mr, mb, rf);

    // Pair 0 emits (rows y0, y0+1)
    emit_row(ra, mn, mx, oimg + (size_t)y0 * W + cb);        // ra dead
    emit_row(rd, mn, mx, oimg + (size_t)(y0 + 1) * W + cb);  // mn,mx dead

    // Pair 1: sort2(rd, re), emits rows y0+2, y0+3
    #pragma unroll
    for (int i = 0; i < 6; i++) {
        mn[i] = fminf(rd[i], re[i]);
        mx[i] = fmaxf(rd[i], re[i]);
    }
    emit_row(rc, mn, mx, oimg + (size_t)(y0 + 2) * W + cb);
    emit_row(rf, mn, mx, oimg + (size_t)(y0 + 3) * W + cb);
}

extern "C" void kernel_launch(void* const* d_in, const int* in_sizes, int n_in,
                              void* d_out, int out_size) {
    const float* x = (const float*)d_in[0];
    float* out = (float*)d_out;

    const int total_threads = (NIMG * H * W) / 16;   // 1,572,864
    const int block = 256;
    const int grid = total_threads / block;           // 6144
    median3x3_kernel<<<grid, block>>>(x, out);
}